// round 3
// baseline (speedup 1.0000x reference)
#include <cuda_runtime.h>
#include <math.h>

// Problem constants
#define BATCH   4
#define NNODES  325
#define BN      (BATCH * NNODES)   // 1300
#define IDIM    64
#define HDIM    128
#define G4H     (4 * HDIM)         // 512
#define MAXNB   96
#define LN_EPS  1e-5f

// ---------------- scratch (__device__ globals; no allocation) ----------------
__device__ float g_gates[BN * G4H];
__device__ float g_h_lstm[BN * HDIM];
__device__ float g_support[BN * HDIM];
__device__ float g_hgraph[BN * HDIM];
__device__ float g_s[BN * HDIM];
__device__ float g_t[BN * HDIM];
__device__ int   g_nbr[BN * MAXNB];
__device__ float g_nbrw[BN * MAXNB];
__device__ int   g_cnt[BN];

__device__ __forceinline__ float sigm(float x) { return 1.0f / (1.0f + expf(-x)); }

// ============================================================================
// K1: LSTM gates GEMM.  gates = x @ W_ih^T + h @ W_hh^T + b.
// Grid (ceil(BN/8), 4): blockIdx.y = gate group (128 rows each).
// 128 threads, one gate-row per thread, 8 nodes per block.
// ============================================================================
#define LNT 8
__global__ void __launch_bounds__(128)
lstm_gemm_kernel(const float* __restrict__ x, const float* __restrict__ h,
                 const float* __restrict__ W_ih, const float* __restrict__ W_hh,
                 const float* __restrict__ b_ih, const float* __restrict__ b_hh)
{
    __shared__ __align__(16) float sx[LNT][IDIM];
    __shared__ __align__(16) float sh[LNT][HDIM];

    const int node0 = blockIdx.x * LNT;
    const int o = threadIdx.x;
    const int g = blockIdx.y * HDIM + o;   // global gate row

    for (int idx = o; idx < LNT * IDIM; idx += 128) {
        int m = idx >> 6, k = idx & 63;
        int node = node0 + m;
        sx[m][k] = (node < BN) ? x[node * IDIM + k] : 0.0f;
    }
    for (int idx = o; idx < LNT * HDIM; idx += 128) {
        int m = idx >> 7, k = idx & 127;
        int node = node0 + m;
        sh[m][k] = (node < BN) ? h[node * HDIM + k] : 0.0f;
    }
    __syncthreads();

    float acc[LNT];
    const float bb = __ldg(b_ih + g) + __ldg(b_hh + g);
#pragma unroll
    for (int m = 0; m < LNT; m++) acc[m] = bb;

    const float4* wx = (const float4*)(W_ih + g * IDIM);
#pragma unroll
    for (int k4 = 0; k4 < IDIM / 4; k4++) {
        float4 w = __ldg(wx + k4);
#pragma unroll
        for (int m = 0; m < LNT; m++) {
            float4 a = *((const float4*)&sx[m][k4 * 4]);
            acc[m] += a.x * w.x + a.y * w.y + a.z * w.z + a.w * w.w;
        }
    }
    const float4* wh = (const float4*)(W_hh + g * HDIM);
#pragma unroll 8
    for (int k4 = 0; k4 < HDIM / 4; k4++) {
        float4 w = __ldg(wh + k4);
#pragma unroll
        for (int m = 0; m < LNT; m++) {
            float4 a = *((const float4*)&sh[m][k4 * 4]);
            acc[m] += a.x * w.x + a.y * w.y + a.z * w.z + a.w * w.w;
        }
    }
#pragma unroll
    for (int m = 0; m < LNT; m++) {
        int node = node0 + m;
        if (node < BN) g_gates[node * G4H + g] = acc[m];
    }
}

// ============================================================================
// K2: LSTM activations (elementwise).
// ============================================================================
__global__ void __launch_bounds__(256)
lstm_act_kernel(const float* __restrict__ c, float* __restrict__ c_out)
{
    int idx = blockIdx.x * 256 + threadIdx.x;
    if (idx >= BN * HDIM) return;
    int node = idx >> 7, u = idx & 127;
    const float* gb = g_gates + node * G4H;
    float ig = sigm(gb[u]);
    float fg = sigm(gb[HDIM + u]);
    float gg = tanhf(gb[2 * HDIM + u]);
    float og = sigm(gb[3 * HDIM + u]);
    float cc = fg * c[idx] + ig * gg;
    g_h_lstm[idx] = og * tanhf(cc);
    c_out[idx] = cc;
}

// ============================================================================
// K3: support = h_lstm @ gc_w   (W (128,128) row-major, not transposed).
// 2 nodes/block -> 650 blocks, 128 threads (one per output column o).
// ============================================================================
__global__ void __launch_bounds__(128)
support_kernel(const float* __restrict__ W)
{
    __shared__ __align__(16) float sA[2][HDIM];
    const int m0 = blockIdx.x * 2;
    const int o = threadIdx.x;

    for (int idx = o; idx < 2 * HDIM; idx += 128) {
        int m = idx >> 7, k = idx & 127;
        sA[m][k] = g_h_lstm[(m0 + m) * HDIM + k];
    }
    __syncthreads();

    float a0 = 0.0f, a1 = 0.0f;
#pragma unroll 8
    for (int k4 = 0; k4 < HDIM / 4; k4++) {
        int k = k4 * 4;
        float w0 = __ldg(W + (k + 0) * HDIM + o);
        float w1 = __ldg(W + (k + 1) * HDIM + o);
        float w2 = __ldg(W + (k + 2) * HDIM + o);
        float w3 = __ldg(W + (k + 3) * HDIM + o);
        float4 p = *((const float4*)&sA[0][k]);
        float4 q = *((const float4*)&sA[1][k]);
        a0 += p.x * w0 + p.y * w1 + p.z * w2 + p.w * w3;
        a1 += q.x * w0 + q.y * w1 + q.z * w2 + q.w * w3;
    }
    g_support[m0 * HDIM + o] = a0;
    g_support[(m0 + 1) * HDIM + o] = a1;
}

// ============================================================================
// K4: sparse graph conv + neighbor-list build.
// One block per (b,i) row.  h_graph[i] = sum_j adj[i,j]*support[j] + gc_b.
// ============================================================================
__global__ void __launch_bounds__(128)
graphconv_kernel(const float* __restrict__ adj, const float* __restrict__ gc_b)
{
    const int row = blockIdx.x;
    const int b = row / NNODES;
    const int i = row % NNODES;
    __shared__ int   cnt;
    __shared__ int   lst[MAXNB];
    __shared__ float wv[MAXNB];

    if (threadIdx.x == 0) cnt = 0;
    __syncthreads();

    const float* arow = adj + (size_t)b * NNODES * NNODES + (size_t)i * NNODES;
    for (int j = threadIdx.x; j < NNODES; j += 128) {
        float a = arow[j];
        if (a != 0.0f) {
            int p = atomicAdd(&cnt, 1);
            if (p < MAXNB) { lst[p] = j; wv[p] = a; }
        }
    }
    __syncthreads();
    const int cn = min(cnt, MAXNB);
    if (threadIdx.x == 0) g_cnt[row] = cn;
    for (int t = threadIdx.x; t < cn; t += 128) {
        g_nbr[row * MAXNB + t] = lst[t];
        g_nbrw[row * MAXNB + t] = wv[t];
    }

    const int u = threadIdx.x;
    float acc = __ldg(gc_b + u);
    for (int t = 0; t < cn; t++)
        acc += wv[t] * g_support[(b * NNODES + lst[t]) * HDIM + u];
    g_hgraph[row * HDIM + u] = acc;
}

// ============================================================================
// K5: s and t in one launch:  s = hg @ Ws^T + bs ; t = hg @ Wt^T + bt.
// Grid (BN/2, 2): blockIdx.y selects Ws vs Wt.  2 nodes/block, 128 threads.
// ============================================================================
__global__ void __launch_bounds__(128)
st_kernel(const float* __restrict__ Ws_w, const float* __restrict__ Ws_b,
          const float* __restrict__ Wt_w, const float* __restrict__ Wt_b)
{
    __shared__ __align__(16) float sA[2][HDIM];
    const int m0 = blockIdx.x * 2;
    const int o = threadIdx.x;
    const float* W    = blockIdx.y ? Wt_w : Ws_w;
    const float* bias = blockIdx.y ? Wt_b : Ws_b;
    float* C          = blockIdx.y ? g_t  : g_s;

    for (int idx = o; idx < 2 * HDIM; idx += 128) {
        int m = idx >> 7, k = idx & 127;
        sA[m][k] = g_hgraph[(m0 + m) * HDIM + k];
    }
    __syncthreads();

    float bs = __ldg(bias + o);
    float a0 = bs, a1 = bs;
    const float4* wrow = (const float4*)(W + o * HDIM);
#pragma unroll 8
    for (int k4 = 0; k4 < HDIM / 4; k4++) {
        float4 w = __ldg(wrow + k4);
        float4 p = *((const float4*)&sA[0][k4 * 4]);
        float4 q = *((const float4*)&sA[1][k4 * 4]);
        a0 += p.x * w.x + p.y * w.y + p.z * w.z + p.w * w.w;
        a1 += q.x * w.x + q.y * w.y + q.z * w.z + q.w * w.w;
    }
    C[m0 * HDIM + o] = a0;
    C[(m0 + 1) * HDIM + o] = a1;
}

// ============================================================================
// K6: fused sparse attention + softmax + context + LayerNorm + combine.
// One block per (b,i) row, 128 threads = 4 warps.
// h_new[row] = [h_lstm | h_att] @ comb_w^T + comb_b  (h_att never hits gmem).
// ============================================================================
__global__ void __launch_bounds__(128)
attn_comb_kernel(const float* __restrict__ v, const float* __restrict__ ln_g,
                 const float* __restrict__ ln_b, const float* __restrict__ comb_w,
                 const float* __restrict__ comb_b, float* __restrict__ out)
{
    const int row = blockIdx.x;
    const int b = row / NNODES;
    const int tid = threadIdx.x;
    const int lane = tid & 31;
    const int wrp = tid >> 5;

    __shared__ float s_sh[HDIM];
    __shared__ float v_sh[HDIM];
    __shared__ __align__(16) float hl_sh[HDIM];
    __shared__ __align__(16) float ha_sh[HDIM];
    __shared__ float sc[MAXNB];
    __shared__ int   lst[MAXNB];
    __shared__ float red1[4], red2[4];

    s_sh[tid] = g_s[row * HDIM + tid];
    v_sh[tid] = __ldg(v + tid);
    hl_sh[tid] = g_h_lstm[row * HDIM + tid];
    const int cnt = g_cnt[row];
    for (int t = tid; t < cnt; t += 128) lst[t] = g_nbr[row * MAXNB + t];
    __syncthreads();

    // scores over neighbors (warp t-strided)
    for (int t = wrp; t < cnt; t += 4) {
        const float* tj = g_t + (size_t)(b * NNODES + lst[t]) * HDIM;
        float p = 0.0f;
#pragma unroll
        for (int q = 0; q < 4; q++) {
            int u = lane + q * 32;
            p += tanhf(s_sh[u] + tj[u]) * v_sh[u];
        }
#pragma unroll
        for (int off = 16; off > 0; off >>= 1)
            p += __shfl_xor_sync(0xffffffffu, p, off);
        if (lane == 0) sc[t] = p;
    }
    __syncthreads();

    // softmax over the cnt real entries (warp 0)
    if (wrp == 0) {
        float mx = -1e30f;
        for (int t = lane; t < cnt; t += 32) mx = fmaxf(mx, sc[t]);
#pragma unroll
        for (int off = 16; off > 0; off >>= 1)
            mx = fmaxf(mx, __shfl_xor_sync(0xffffffffu, mx, off));
        float sm = 0.0f;
        for (int t = lane; t < cnt; t += 32) {
            float e = expf(sc[t] - mx);
            sc[t] = e;
            sm += e;
        }
#pragma unroll
        for (int off = 16; off > 0; off >>= 1)
            sm += __shfl_xor_sync(0xffffffffu, sm, off);
        float inv = 1.0f / sm;
        for (int t = lane; t < cnt; t += 32) sc[t] *= inv;
    }
    __syncthreads();

    // context (thread = feature u)
    const int u = tid;
    float acc = 0.0f;
    for (int t = 0; t < cnt; t++)
        acc += sc[t] * g_hgraph[(size_t)(b * NNODES + lst[t]) * HDIM + u];

    // LayerNorm over H=128
    float s1 = acc, s2 = acc * acc;
#pragma unroll
    for (int off = 16; off > 0; off >>= 1) {
        s1 += __shfl_xor_sync(0xffffffffu, s1, off);
        s2 += __shfl_xor_sync(0xffffffffu, s2, off);
    }
    if (lane == 0) { red1[wrp] = s1; red2[wrp] = s2; }
    __syncthreads();
    float tot1 = red1[0] + red1[1] + red1[2] + red1[3];
    float tot2 = red2[0] + red2[1] + red2[2] + red2[3];
    float mu = tot1 * (1.0f / HDIM);
    float var = tot2 * (1.0f / HDIM) - mu * mu;
    ha_sh[u] = __ldg(ln_g + u) * (acc - mu) * rsqrtf(var + LN_EPS) + __ldg(ln_b + u);
    __syncthreads();

    // combine: out[row,o] = sum_k [hl|ha][k] * comb_w[o,k] + comb_b[o]
    const int o = tid;
    float cacc = __ldg(comb_b + o);
    const float4* wrow = (const float4*)(comb_w + o * 2 * HDIM);
#pragma unroll 8
    for (int k4 = 0; k4 < HDIM / 4; k4++) {
        float4 w = __ldg(wrow + k4);
        float4 a = *((const float4*)&hl_sh[k4 * 4]);
        cacc += a.x * w.x + a.y * w.y + a.z * w.z + a.w * w.w;
    }
#pragma unroll 8
    for (int k4 = 0; k4 < HDIM / 4; k4++) {
        float4 w = __ldg(wrow + HDIM / 4 + k4);
        float4 a = *((const float4*)&ha_sh[k4 * 4]);
        cacc += a.x * w.x + a.y * w.y + a.z * w.z + a.w * w.w;
    }
    out[row * HDIM + o] = cacc;
}

// ============================================================================
extern "C" void kernel_launch(void* const* d_in, const int* in_sizes, int n_in,
                              void* d_out, int out_size)
{
    const float* x      = (const float*)d_in[0];
    const float* adj    = (const float*)d_in[1];
    const float* h      = (const float*)d_in[2];
    const float* c      = (const float*)d_in[3];
    const float* W_ih   = (const float*)d_in[4];
    const float* W_hh   = (const float*)d_in[5];
    const float* b_ih   = (const float*)d_in[6];
    const float* b_hh   = (const float*)d_in[7];
    const float* gc_w   = (const float*)d_in[8];
    const float* gc_b   = (const float*)d_in[9];
    const float* Ws_w   = (const float*)d_in[10];
    const float* Ws_b   = (const float*)d_in[11];
    const float* Wt_w   = (const float*)d_in[12];
    const float* Wt_b   = (const float*)d_in[13];
    const float* v      = (const float*)d_in[14];
    const float* ln_g   = (const float*)d_in[15];
    const float* ln_b   = (const float*)d_in[16];
    const float* comb_w = (const float*)d_in[17];
    const float* comb_b = (const float*)d_in[18];

    float* out = (float*)d_out;              // [0, BN*H) = h_new, then c_lstm
    float* c_out = out + (size_t)BN * HDIM;

    dim3 lstm_grid((BN + LNT - 1) / LNT, 4);          // 163 x 4 = 652 blocks
    lstm_gemm_kernel<<<lstm_grid, 128>>>(x, h, W_ih, W_hh, b_ih, b_hh);
    lstm_act_kernel<<<(BN * HDIM + 255) / 256, 256>>>(c, c_out);
    support_kernel<<<BN / 2, 128>>>(gc_w);            // 650 blocks
    graphconv_kernel<<<BN, 128>>>(adj, gc_b);         // 1300 blocks
    dim3 st_grid(BN / 2, 2);                          // 650 x 2 = 1300 blocks
    st_kernel<<<st_grid, 128>>>(Ws_w, Ws_b, Wt_w, Wt_b);
    attn_comb_kernel<<<BN, 128>>>(v, ln_g, ln_b, comb_w, comb_b, out);
}

// round 4
// speedup vs baseline: 1.2279x; 1.2279x over previous
#include <cuda_runtime.h>
#include <math.h>

// Problem constants
#define BATCH   4
#define NNODES  325
#define BN      (BATCH * NNODES)   // 1300
#define IDIM    64
#define HDIM    128
#define G4H     (4 * HDIM)         // 512
#define MAXNB   96
#define LN_EPS  1e-5f

// ---------------- scratch (__device__ globals; no allocation) ----------------
__device__ float g_gates[BN * G4H];
__device__ float g_h_lstm[BN * HDIM];
__device__ float g_support[BN * HDIM];
__device__ float g_hgraph[BN * HDIM];
__device__ float g_s[BN * HDIM];
__device__ float g_t[BN * HDIM];
__device__ int   g_nbr[BN * MAXNB];
__device__ int   g_cnt[BN];
// transposed weights (coalesced GEMM access: Wt[k*O + o])
__device__ float g_Wih_t[IDIM * G4H];     // [64][512]
__device__ float g_Whh_t[HDIM * G4H];     // [128][512]
__device__ float g_Ws_t[HDIM * HDIM];     // [128][128]
__device__ float g_Wt_t[HDIM * HDIM];     // [128][128]
__device__ float g_comb_t[2 * HDIM * HDIM]; // [256][128]

__device__ __forceinline__ float sigm_fast(float x) {
    return __fdividef(1.0f, 1.0f + __expf(-x));
}
__device__ __forceinline__ float tanh_fast(float x) {
    float cx = fminf(fmaxf(x, -15.0f), 15.0f);
    float e = __expf(2.0f * cx);
    return __fdividef(e - 1.0f, e + 1.0f);
}

// ============================================================================
// K0: weight transposes (coalesced writes).
// ============================================================================
#define TW_TOTAL (IDIM*G4H + HDIM*G4H + 2*HDIM*HDIM + 2*HDIM*HDIM)
__global__ void __launch_bounds__(256)
transpose_kernel(const float* __restrict__ W_ih, const float* __restrict__ W_hh,
                 const float* __restrict__ Ws_w, const float* __restrict__ Wt_w,
                 const float* __restrict__ comb_w)
{
    int idx = blockIdx.x * 256 + threadIdx.x;
    if (idx < IDIM * G4H) {                       // Wih_t [64][512]
        int k = idx >> 9, g = idx & 511;
        g_Wih_t[idx] = __ldg(W_ih + g * IDIM + k);
        return;
    }
    idx -= IDIM * G4H;
    if (idx < HDIM * G4H) {                       // Whh_t [128][512]
        int k = idx >> 9, g = idx & 511;
        g_Whh_t[idx] = __ldg(W_hh + g * HDIM + k);
        return;
    }
    idx -= HDIM * G4H;
    if (idx < HDIM * HDIM) {                      // Ws_t [128][128]
        int k = idx >> 7, o = idx & 127;
        g_Ws_t[idx] = __ldg(Ws_w + o * HDIM + k);
        return;
    }
    idx -= HDIM * HDIM;
    if (idx < HDIM * HDIM) {                      // Wt_t [128][128]
        int k = idx >> 7, o = idx & 127;
        g_Wt_t[idx] = __ldg(Wt_w + o * HDIM + k);
        return;
    }
    idx -= HDIM * HDIM;
    if (idx < 2 * HDIM * HDIM) {                  // comb_t [256][128]
        int k = idx >> 7, o = idx & 127;
        g_comb_t[idx] = __ldg(comb_w + o * 2 * HDIM + k);
    }
}

// ============================================================================
// K1: LSTM gates GEMM.  gates = x @ W_ih^T + h @ W_hh^T + b.
// Grid (ceil(BN/8), 4).  Thread o -> gate row g = by*128+o.  8 nodes/block.
// Coalesced weight reads via g_W*_t[k*512 + g].
// ============================================================================
#define LNT 8
__global__ void __launch_bounds__(128)
lstm_gemm_kernel(const float* __restrict__ x, const float* __restrict__ h,
                 const float* __restrict__ b_ih, const float* __restrict__ b_hh)
{
    __shared__ __align__(16) float sx[LNT][IDIM];
    __shared__ __align__(16) float sh[LNT][HDIM];

    const int node0 = blockIdx.x * LNT;
    const int o = threadIdx.x;
    const int g = blockIdx.y * HDIM + o;

    for (int idx = o; idx < LNT * IDIM; idx += 128) {
        int m = idx >> 6, k = idx & 63;
        int node = node0 + m;
        sx[m][k] = (node < BN) ? x[node * IDIM + k] : 0.0f;
    }
    for (int idx = o; idx < LNT * HDIM; idx += 128) {
        int m = idx >> 7, k = idx & 127;
        int node = node0 + m;
        sh[m][k] = (node < BN) ? h[node * HDIM + k] : 0.0f;
    }
    __syncthreads();

    float acc[LNT];
    const float bb = __ldg(b_ih + g) + __ldg(b_hh + g);
#pragma unroll
    for (int m = 0; m < LNT; m++) acc[m] = bb;

#pragma unroll 4
    for (int k4 = 0; k4 < IDIM / 4; k4++) {
        int k = k4 * 4;
        float w0 = g_Wih_t[(k + 0) * G4H + g];
        float w1 = g_Wih_t[(k + 1) * G4H + g];
        float w2 = g_Wih_t[(k + 2) * G4H + g];
        float w3 = g_Wih_t[(k + 3) * G4H + g];
#pragma unroll
        for (int m = 0; m < LNT; m++) {
            float4 a = *((const float4*)&sx[m][k]);
            acc[m] += a.x * w0 + a.y * w1 + a.z * w2 + a.w * w3;
        }
    }
#pragma unroll 4
    for (int k4 = 0; k4 < HDIM / 4; k4++) {
        int k = k4 * 4;
        float w0 = g_Whh_t[(k + 0) * G4H + g];
        float w1 = g_Whh_t[(k + 1) * G4H + g];
        float w2 = g_Whh_t[(k + 2) * G4H + g];
        float w3 = g_Whh_t[(k + 3) * G4H + g];
#pragma unroll
        for (int m = 0; m < LNT; m++) {
            float4 a = *((const float4*)&sh[m][k]);
            acc[m] += a.x * w0 + a.y * w1 + a.z * w2 + a.w * w3;
        }
    }
#pragma unroll
    for (int m = 0; m < LNT; m++) {
        int node = node0 + m;
        if (node < BN) g_gates[node * G4H + g] = acc[m];
    }
}

// ============================================================================
// K2: LSTM activations + support GEMM fused.  4 nodes/block, 325 blocks.
// ============================================================================
__global__ void __launch_bounds__(128)
act_support_kernel(const float* __restrict__ c, const float* __restrict__ gc_w,
                   float* __restrict__ c_out)
{
    __shared__ __align__(16) float shh[4][HDIM];
    const int node0 = blockIdx.x * 4;
    const int u = threadIdx.x;

#pragma unroll
    for (int m = 0; m < 4; m++) {
        int node = node0 + m;
        const float* gb = g_gates + node * G4H;
        float ig = sigm_fast(gb[u]);
        float fg = sigm_fast(gb[HDIM + u]);
        float gg = tanh_fast(gb[2 * HDIM + u]);
        float og = sigm_fast(gb[3 * HDIM + u]);
        float cc = fg * c[node * HDIM + u] + ig * gg;
        float hh = og * tanh_fast(cc);
        c_out[node * HDIM + u] = cc;
        g_h_lstm[node * HDIM + u] = hh;
        shh[m][u] = hh;
    }
    __syncthreads();

    // support = h_lstm @ gc_w  (gc_w[k][o] already coalesced)
    const int o = u;
    float acc[4] = {0.f, 0.f, 0.f, 0.f};
#pragma unroll 8
    for (int k4 = 0; k4 < HDIM / 4; k4++) {
        int k = k4 * 4;
        float w0 = __ldg(gc_w + (k + 0) * HDIM + o);
        float w1 = __ldg(gc_w + (k + 1) * HDIM + o);
        float w2 = __ldg(gc_w + (k + 2) * HDIM + o);
        float w3 = __ldg(gc_w + (k + 3) * HDIM + o);
#pragma unroll
        for (int m = 0; m < 4; m++) {
            float4 a = *((const float4*)&shh[m][k]);
            acc[m] += a.x * w0 + a.y * w1 + a.z * w2 + a.w * w3;
        }
    }
#pragma unroll
    for (int m = 0; m < 4; m++)
        g_support[(node0 + m) * HDIM + o] = acc[m];
}

// ============================================================================
// K3: graphconv (warp-per-row) + fused s/t GEMM (m=4).  325 blocks, 128 thr.
// ============================================================================
__global__ void __launch_bounds__(128)
graphconv_st_kernel(const float* __restrict__ adj, const float* __restrict__ gc_b,
                    const float* __restrict__ Ws_b, const float* __restrict__ Wt_b)
{
    const int row0 = blockIdx.x * 4;
    const int tid = threadIdx.x;
    const int lane = tid & 31;
    const int wrp = tid >> 5;
    const int row = row0 + wrp;
    const int b = row / NNODES;
    const int i = row % NNODES;

    __shared__ int   cnt[4];
    __shared__ int   lst[4][MAXNB];
    __shared__ float wv[4][MAXNB];
    __shared__ __align__(16) float hg_sh[4][HDIM];

    if (lane == 0) cnt[wrp] = 0;
    __syncwarp();

    const float* arow = adj + (size_t)b * NNODES * NNODES + (size_t)i * NNODES;
    for (int j = lane; j < NNODES; j += 32) {
        float a = __ldg(arow + j);
        if (a != 0.0f) {
            int p = atomicAdd(&cnt[wrp], 1);
            if (p < MAXNB) { lst[wrp][p] = j; wv[wrp][p] = a; }
        }
    }
    __syncwarp();
    const int cn = min(cnt[wrp], MAXNB);
    if (lane == 0) g_cnt[row] = cn;
    for (int t = lane; t < cn; t += 32) g_nbr[row * MAXNB + t] = lst[wrp][t];

    // gather: lane owns u = lane + q*32
    float acc[4];
#pragma unroll
    for (int q = 0; q < 4; q++) acc[q] = __ldg(gc_b + lane + q * 32);
    const float* supb = g_support + (size_t)b * NNODES * HDIM;
    for (int t = 0; t < cn; t++) {
        const float* sp = supb + (size_t)lst[wrp][t] * HDIM;
        float w = wv[wrp][t];
#pragma unroll
        for (int q = 0; q < 4; q++)
            acc[q] += w * __ldg(sp + lane + q * 32);
    }
#pragma unroll
    for (int q = 0; q < 4; q++) {
        int u = lane + q * 32;
        hg_sh[wrp][u] = acc[q];
        g_hgraph[row * HDIM + u] = acc[q];
    }
    __syncthreads();

    // s/t GEMM: 4 rows, thread = output col o, coalesced weight reads
    const int o = tid;
    float sa[4], ta[4];
    float bs = __ldg(Ws_b + o), bt = __ldg(Wt_b + o);
#pragma unroll
    for (int m = 0; m < 4; m++) { sa[m] = bs; ta[m] = bt; }
#pragma unroll 4
    for (int k4 = 0; k4 < HDIM / 4; k4++) {
        int k = k4 * 4;
        float ws0 = g_Ws_t[(k + 0) * HDIM + o];
        float ws1 = g_Ws_t[(k + 1) * HDIM + o];
        float ws2 = g_Ws_t[(k + 2) * HDIM + o];
        float ws3 = g_Ws_t[(k + 3) * HDIM + o];
        float wt0 = g_Wt_t[(k + 0) * HDIM + o];
        float wt1 = g_Wt_t[(k + 1) * HDIM + o];
        float wt2 = g_Wt_t[(k + 2) * HDIM + o];
        float wt3 = g_Wt_t[(k + 3) * HDIM + o];
#pragma unroll
        for (int m = 0; m < 4; m++) {
            float4 a = *((const float4*)&hg_sh[m][k]);
            sa[m] += a.x * ws0 + a.y * ws1 + a.z * ws2 + a.w * ws3;
            ta[m] += a.x * wt0 + a.y * wt1 + a.z * wt2 + a.w * wt3;
        }
    }
#pragma unroll
    for (int m = 0; m < 4; m++) {
        g_s[(row0 + m) * HDIM + o] = sa[m];
        g_t[(row0 + m) * HDIM + o] = ta[m];
    }
}

// ============================================================================
// K4: attention (warp-per-row) + LayerNorm + fused combine GEMM (m=4).
// 325 blocks, 128 threads.
// ============================================================================
__global__ void __launch_bounds__(128)
attn_comb_kernel(const float* __restrict__ v, const float* __restrict__ ln_g,
                 const float* __restrict__ ln_b, const float* __restrict__ comb_b,
                 float* __restrict__ out)
{
    const int row0 = blockIdx.x * 4;
    const int tid = threadIdx.x;
    const int lane = tid & 31;
    const int wrp = tid >> 5;
    const int row = row0 + wrp;
    const int b = row / NNODES;

    __shared__ int   lst[4][MAXNB];
    __shared__ float sc[4][MAXNB];
    __shared__ __align__(16) float hl_sh[4][HDIM];
    __shared__ __align__(16) float ha_sh[4][HDIM];

    // block-wide: stage h_lstm rows for combine
    for (int idx = tid; idx < 4 * HDIM; idx += 128) {
        int m = idx >> 7, k = idx & 127;
        hl_sh[m][k] = g_h_lstm[(row0 + m) * HDIM + k];
    }

    // per-warp: row state
    float sreg[4], vreg[4];
#pragma unroll
    for (int q = 0; q < 4; q++) {
        int u = lane + q * 32;
        sreg[q] = g_s[row * HDIM + u];
        vreg[q] = __ldg(v + u);
    }
    const int cn = g_cnt[row];
    for (int t = lane; t < cn; t += 32) lst[wrp][t] = g_nbr[row * MAXNB + t];
    __syncwarp();

    // scores
    const float* tb = g_t + (size_t)b * NNODES * HDIM;
    for (int t = 0; t < cn; t++) {
        const float* tj = tb + (size_t)lst[wrp][t] * HDIM;
        float p = 0.0f;
#pragma unroll
        for (int q = 0; q < 4; q++)
            p += tanh_fast(sreg[q] + __ldg(tj + lane + q * 32)) * vreg[q];
#pragma unroll
        for (int off = 16; off > 0; off >>= 1)
            p += __shfl_xor_sync(0xffffffffu, p, off);
        if (lane == 0) sc[wrp][t] = p;
    }
    __syncwarp();

    // softmax (warp-local)
    float mx = -1e30f;
    for (int t = lane; t < cn; t += 32) mx = fmaxf(mx, sc[wrp][t]);
#pragma unroll
    for (int off = 16; off > 0; off >>= 1)
        mx = fmaxf(mx, __shfl_xor_sync(0xffffffffu, mx, off));
    float sm = 0.0f;
    for (int t = lane; t < cn; t += 32) {
        float e = __expf(sc[wrp][t] - mx);
        sc[wrp][t] = e;
        sm += e;
    }
#pragma unroll
    for (int off = 16; off > 0; off >>= 1)
        sm += __shfl_xor_sync(0xffffffffu, sm, off);
    float inv = __fdividef(1.0f, sm);
    __syncwarp();

    // context
    float accq[4] = {0.f, 0.f, 0.f, 0.f};
    const float* hgb = g_hgraph + (size_t)b * NNODES * HDIM;
    for (int t = 0; t < cn; t++) {
        float w = sc[wrp][t] * inv;
        const float* hj = hgb + (size_t)lst[wrp][t] * HDIM;
#pragma unroll
        for (int q = 0; q < 4; q++)
            accq[q] += w * __ldg(hj + lane + q * 32);
    }

    // LayerNorm (warp holds all 128 features)
    float s1 = accq[0] + accq[1] + accq[2] + accq[3];
    float s2 = accq[0]*accq[0] + accq[1]*accq[1] + accq[2]*accq[2] + accq[3]*accq[3];
#pragma unroll
    for (int off = 16; off > 0; off >>= 1) {
        s1 += __shfl_xor_sync(0xffffffffu, s1, off);
        s2 += __shfl_xor_sync(0xffffffffu, s2, off);
    }
    float mu = s1 * (1.0f / HDIM);
    float var = s2 * (1.0f / HDIM) - mu * mu;
    float rs = rsqrtf(var + LN_EPS);
#pragma unroll
    for (int q = 0; q < 4; q++) {
        int u = lane + q * 32;
        ha_sh[wrp][u] = __ldg(ln_g + u) * (accq[q] - mu) * rs + __ldg(ln_b + u);
    }
    __syncthreads();

    // combine: out[row_m, o] = [hl|ha] @ comb_t + comb_b
    const int o = tid;
    float cb = __ldg(comb_b + o);
    float cacc[4];
#pragma unroll
    for (int m = 0; m < 4; m++) cacc[m] = cb;
#pragma unroll 4
    for (int k4 = 0; k4 < HDIM / 4; k4++) {
        int k = k4 * 4;
        float w0 = g_comb_t[(k + 0) * HDIM + o];
        float w1 = g_comb_t[(k + 1) * HDIM + o];
        float w2 = g_comb_t[(k + 2) * HDIM + o];
        float w3 = g_comb_t[(k + 3) * HDIM + o];
#pragma unroll
        for (int m = 0; m < 4; m++) {
            float4 a = *((const float4*)&hl_sh[m][k]);
            cacc[m] += a.x * w0 + a.y * w1 + a.z * w2 + a.w * w3;
        }
    }
#pragma unroll 4
    for (int k4 = 0; k4 < HDIM / 4; k4++) {
        int k = k4 * 4;
        float w0 = g_comb_t[(HDIM + k + 0) * HDIM + o];
        float w1 = g_comb_t[(HDIM + k + 1) * HDIM + o];
        float w2 = g_comb_t[(HDIM + k + 2) * HDIM + o];
        float w3 = g_comb_t[(HDIM + k + 3) * HDIM + o];
#pragma unroll
        for (int m = 0; m < 4; m++) {
            float4 a = *((const float4*)&ha_sh[m][k]);
            cacc[m] += a.x * w0 + a.y * w1 + a.z * w2 + a.w * w3;
        }
    }
#pragma unroll
    for (int m = 0; m < 4; m++)
        out[(row0 + m) * HDIM + o] = cacc[m];
}

// ============================================================================
extern "C" void kernel_launch(void* const* d_in, const int* in_sizes, int n_in,
                              void* d_out, int out_size)
{
    const float* x      = (const float*)d_in[0];
    const float* adj    = (const float*)d_in[1];
    const float* h      = (const float*)d_in[2];
    const float* c      = (const float*)d_in[3];
    const float* W_ih   = (const float*)d_in[4];
    const float* W_hh   = (const float*)d_in[5];
    const float* b_ih   = (const float*)d_in[6];
    const float* b_hh   = (const float*)d_in[7];
    const float* gc_w   = (const float*)d_in[8];
    const float* gc_b   = (const float*)d_in[9];
    const float* Ws_w   = (const float*)d_in[10];
    const float* Ws_b   = (const float*)d_in[11];
    const float* Wt_w   = (const float*)d_in[12];
    const float* Wt_b   = (const float*)d_in[13];
    const float* v      = (const float*)d_in[14];
    const float* ln_g   = (const float*)d_in[15];
    const float* ln_b   = (const float*)d_in[16];
    const float* comb_w = (const float*)d_in[17];
    const float* comb_b = (const float*)d_in[18];

    float* out = (float*)d_out;              // h_new, then c_lstm
    float* c_out = out + (size_t)BN * HDIM;

    transpose_kernel<<<(TW_TOTAL + 255) / 256, 256>>>(W_ih, W_hh, Ws_w, Wt_w, comb_w);
    dim3 lstm_grid((BN + LNT - 1) / LNT, 4);          // 163 x 4
    lstm_gemm_kernel<<<lstm_grid, 128>>>(x, h, b_ih, b_hh);
    act_support_kernel<<<BN / 4, 128>>>(c, gc_w, c_out);     // 325
    graphconv_st_kernel<<<BN / 4, 128>>>(adj, gc_b, Ws_b, Wt_b); // 325
    attn_comb_kernel<<<BN / 4, 128>>>(v, ln_g, ln_b, comb_b, out); // 325
}

// round 6
// speedup vs baseline: 1.7824x; 1.4516x over previous
#include <cuda_runtime.h>
#include <math.h>

// Problem constants
#define BATCH   4
#define NNODES  325
#define BN      (BATCH * NNODES)   // 1300
#define IDIM    64
#define HDIM    128
#define G4H     (4 * HDIM)         // 512
#define MAXNB   96
#define LN_EPS  1e-5f

// ---------------- scratch (__device__ globals; no allocation) ----------------
__device__ float g_gates[BN * G4H];
__device__ float g_h_lstm[BN * HDIM];
__device__ float g_support[BN * HDIM];
__device__ float g_hgraph[BN * HDIM];
__device__ float g_s[BN * HDIM];
__device__ float g_t[BN * HDIM];
__device__ int   g_nbr[BN * MAXNB];
__device__ float g_nbrw[BN * MAXNB];
__device__ int   g_cnt[BN];
// transposed weights (coalesced GEMM access: Wt[k*O + o])
__device__ float g_Wih_t[IDIM * G4H];       // [64][512]
__device__ float g_Whh_t[HDIM * G4H];       // [128][512]
__device__ float g_Ws_t[HDIM * HDIM];       // [128][128]
__device__ float g_Wt_t[HDIM * HDIM];       // [128][128]
__device__ float g_comb_t[2 * HDIM * HDIM]; // [256][128]

__device__ __forceinline__ float sigm_fast(float x) {
    return __fdividef(1.0f, 1.0f + __expf(-x));
}
__device__ __forceinline__ float tanh_fast(float x) {
    float cx = fminf(fmaxf(x, -15.0f), 15.0f);
    float e = __expf(2.0f * cx);
    return __fdividef(e - 1.0f, e + 1.0f);
}

// ============================================================================
// K0: prep = weight transposes + adjacency neighbor-list build (one launch).
// Blocks [0, NTB): transpose (256 thr).  Blocks [NTB, NTB+325): scan 4 rows,
// one warp per row, ballot-ordered compaction (deterministic).
// ============================================================================
#define TW_TOTAL (IDIM*G4H + HDIM*G4H + 2*HDIM*HDIM + 2*HDIM*HDIM)
#define NTB ((TW_TOTAL + 255) / 256)   // 640
__global__ void __launch_bounds__(256)
prep_kernel(const float* __restrict__ W_ih, const float* __restrict__ W_hh,
            const float* __restrict__ Ws_w, const float* __restrict__ Wt_w,
            const float* __restrict__ comb_w, const float* __restrict__ adj)
{
    if (blockIdx.x < NTB) {
        int idx = blockIdx.x * 256 + threadIdx.x;
        if (idx < IDIM * G4H) {                       // Wih_t [64][512]
            int k = idx >> 9, g = idx & 511;
            g_Wih_t[idx] = __ldg(W_ih + g * IDIM + k);
            return;
        }
        idx -= IDIM * G4H;
        if (idx < HDIM * G4H) {                       // Whh_t [128][512]
            int k = idx >> 9, g = idx & 511;
            g_Whh_t[idx] = __ldg(W_hh + g * HDIM + k);
            return;
        }
        idx -= HDIM * G4H;
        if (idx < HDIM * HDIM) {                      // Ws_t [128][128]
            int k = idx >> 7, o = idx & 127;
            g_Ws_t[idx] = __ldg(Ws_w + o * HDIM + k);
            return;
        }
        idx -= HDIM * HDIM;
        if (idx < HDIM * HDIM) {                      // Wt_t [128][128]
            int k = idx >> 7, o = idx & 127;
            g_Wt_t[idx] = __ldg(Wt_w + o * HDIM + k);
            return;
        }
        idx -= HDIM * HDIM;
        if (idx < 2 * HDIM * HDIM) {                  // comb_t [256][128]
            int k = idx >> 7, o = idx & 127;
            g_comb_t[idx] = __ldg(comb_w + o * 2 * HDIM + k);
        }
        return;
    }

    // ---- adjacency scan: 8 warps, one row per warp ----
    const int lane = threadIdx.x & 31;
    const int wrp  = threadIdx.x >> 5;
    const int row  = (blockIdx.x - NTB) * 8 + wrp;
    if (row >= BN) return;
    const int b = row / NNODES;
    const int i = row % NNODES;
    const float* arow = adj + (size_t)b * NNODES * NNODES + (size_t)i * NNODES;

    int cnt = 0;
    const unsigned lt = (1u << lane) - 1u;
    for (int j0 = 0; j0 < NNODES; j0 += 32) {
        int j = j0 + lane;
        float a = (j < NNODES) ? __ldg(arow + j) : 0.0f;
        unsigned m = __ballot_sync(0xffffffffu, a != 0.0f);
        int pos = cnt + __popc(m & lt);
        if (a != 0.0f && pos < MAXNB) {
            g_nbr[row * MAXNB + pos]  = j;
            g_nbrw[row * MAXNB + pos] = a;
        }
        cnt += __popc(m);
    }
    if (lane == 0) g_cnt[row] = min(cnt, MAXNB);
}

// ============================================================================
// K1: LSTM gates GEMM.  gates = x @ W_ih^T + h @ W_hh^T + b.
// Grid (163, 4), 128 thr, 8 nodes/block, coalesced transposed weights.
// ============================================================================
#define LNT 8
__global__ void __launch_bounds__(128)
lstm_gemm_kernel(const float* __restrict__ x, const float* __restrict__ h,
                 const float* __restrict__ b_ih, const float* __restrict__ b_hh)
{
    __shared__ __align__(16) float sx[LNT][IDIM];
    __shared__ __align__(16) float sh[LNT][HDIM];

    const int node0 = blockIdx.x * LNT;
    const int o = threadIdx.x;
    const int g = blockIdx.y * HDIM + o;

    for (int idx = o; idx < LNT * IDIM; idx += 128) {
        int m = idx >> 6, k = idx & 63;
        int node = node0 + m;
        sx[m][k] = (node < BN) ? x[node * IDIM + k] : 0.0f;
    }
    for (int idx = o; idx < LNT * HDIM; idx += 128) {
        int m = idx >> 7, k = idx & 127;
        int node = node0 + m;
        sh[m][k] = (node < BN) ? h[node * HDIM + k] : 0.0f;
    }
    __syncthreads();

    float acc[LNT];
    const float bb = __ldg(b_ih + g) + __ldg(b_hh + g);
#pragma unroll
    for (int m = 0; m < LNT; m++) acc[m] = bb;

#pragma unroll 4
    for (int k4 = 0; k4 < IDIM / 4; k4++) {
        int k = k4 * 4;
        float w0 = g_Wih_t[(k + 0) * G4H + g];
        float w1 = g_Wih_t[(k + 1) * G4H + g];
        float w2 = g_Wih_t[(k + 2) * G4H + g];
        float w3 = g_Wih_t[(k + 3) * G4H + g];
#pragma unroll
        for (int m = 0; m < LNT; m++) {
            float4 a = *((const float4*)&sx[m][k]);
            acc[m] += a.x * w0 + a.y * w1 + a.z * w2 + a.w * w3;
        }
    }
#pragma unroll 4
    for (int k4 = 0; k4 < HDIM / 4; k4++) {
        int k = k4 * 4;
        float w0 = g_Whh_t[(k + 0) * G4H + g];
        float w1 = g_Whh_t[(k + 1) * G4H + g];
        float w2 = g_Whh_t[(k + 2) * G4H + g];
        float w3 = g_Whh_t[(k + 3) * G4H + g];
#pragma unroll
        for (int m = 0; m < LNT; m++) {
            float4 a = *((const float4*)&sh[m][k]);
            acc[m] += a.x * w0 + a.y * w1 + a.z * w2 + a.w * w3;
        }
    }
#pragma unroll
    for (int m = 0; m < LNT; m++) {
        int node = node0 + m;
        if (node < BN) g_gates[node * G4H + g] = acc[m];
    }
}

// ============================================================================
// K2: LSTM activations + support GEMM (m=2).  650 blocks, 128 threads.
// ============================================================================
__global__ void __launch_bounds__(128)
act_support_kernel(const float* __restrict__ c, const float* __restrict__ gc_w,
                   float* __restrict__ c_out)
{
    __shared__ float shh[2][HDIM];
    const int node0 = blockIdx.x * 2;
    const int u = threadIdx.x;

#pragma unroll
    for (int m = 0; m < 2; m++) {
        int node = node0 + m;
        const float* gb = g_gates + node * G4H;
        float ig = sigm_fast(gb[u]);
        float fg = sigm_fast(gb[HDIM + u]);
        float gg = tanh_fast(gb[2 * HDIM + u]);
        float og = sigm_fast(gb[3 * HDIM + u]);
        float cc = fg * c[node * HDIM + u] + ig * gg;
        float hh = og * tanh_fast(cc);
        c_out[node * HDIM + u] = cc;
        g_h_lstm[node * HDIM + u] = hh;
        shh[m][u] = hh;
    }
    __syncthreads();

    const int o = u;
    float a0 = 0.f, a1 = 0.f;
#pragma unroll 4
    for (int k = 0; k < HDIM; k++) {
        float w = __ldg(gc_w + k * HDIM + o);
        a0 += shh[0][k] * w;
        a1 += shh[1][k] * w;
    }
    g_support[node0 * HDIM + o] = a0;
    g_support[(node0 + 1) * HDIM + o] = a1;
}

// ============================================================================
// K3: graph conv gather + fused s/t GEMM (m=1).  Block-per-row: 1300 blocks.
// ============================================================================
__global__ void __launch_bounds__(128)
graphconv_st_kernel(const float* __restrict__ gc_b, const float* __restrict__ Ws_b,
                    const float* __restrict__ Wt_b)
{
    const int row = blockIdx.x;
    const int b = row / NNODES;
    const int tid = threadIdx.x;

    __shared__ int   lst[MAXNB];
    __shared__ float wv[MAXNB];
    __shared__ float hg[HDIM];

    const int cn = g_cnt[row];
    for (int t = tid; t < cn; t += 128) {
        lst[t] = g_nbr[row * MAXNB + t];
        wv[t]  = g_nbrw[row * MAXNB + t];
    }
    __syncthreads();

    // gather: thread = feature u, coalesced 512B loads per neighbor
    const int u = tid;
    float acc = __ldg(gc_b + u);
    const float* supb = g_support + (size_t)b * NNODES * HDIM;
    for (int t = 0; t < cn; t++)
        acc += wv[t] * __ldg(supb + (size_t)lst[t] * HDIM + u);
    hg[u] = acc;
    g_hgraph[row * HDIM + u] = acc;
    __syncthreads();

    // s/t GEMM (m=1): thread = output col o; hg broadcast from shared
    const int o = tid;
    float sa = __ldg(Ws_b + o);
    float ta = __ldg(Wt_b + o);
#pragma unroll 8
    for (int k = 0; k < HDIM; k++) {
        float hk = hg[k];
        sa += hk * g_Ws_t[k * HDIM + o];
        ta += hk * g_Wt_t[k * HDIM + o];
    }
    g_s[row * HDIM + o] = sa;
    g_t[row * HDIM + o] = ta;
}

// ============================================================================
// K4: attention + softmax + context + LayerNorm + combine (m=1).
// Block-per-row: 1300 blocks, 128 threads = 4 warps.
// ============================================================================
__global__ void __launch_bounds__(128)
attn_comb_kernel(const float* __restrict__ v, const float* __restrict__ ln_g,
                 const float* __restrict__ ln_b, const float* __restrict__ comb_b,
                 float* __restrict__ out)
{
    const int row = blockIdx.x;
    const int b = row / NNODES;
    const int tid = threadIdx.x;
    const int lane = tid & 31;
    const int wrp = tid >> 5;

    __shared__ float s_sh[HDIM];
    __shared__ float v_sh[HDIM];
    __shared__ float hl_sh[HDIM];
    __shared__ float ha_sh[HDIM];
    __shared__ float sc[MAXNB];
    __shared__ int   lst[MAXNB];
    __shared__ float red1[4], red2[4];

    s_sh[tid]  = g_s[row * HDIM + tid];
    v_sh[tid]  = __ldg(v + tid);
    hl_sh[tid] = g_h_lstm[row * HDIM + tid];
    const int cn = g_cnt[row];
    for (int t = tid; t < cn; t += 128) lst[t] = g_nbr[row * MAXNB + t];
    __syncthreads();

    // scores: warp t-strided; lanes over features
    const float* tb = g_t + (size_t)b * NNODES * HDIM;
    for (int t = wrp; t < cn; t += 4) {
        const float* tj = tb + (size_t)lst[t] * HDIM;
        float p = 0.0f;
#pragma unroll
        for (int q = 0; q < 4; q++) {
            int u = lane + q * 32;
            p += tanh_fast(s_sh[u] + __ldg(tj + u)) * v_sh[u];
        }
#pragma unroll
        for (int off = 16; off > 0; off >>= 1)
            p += __shfl_xor_sync(0xffffffffu, p, off);
        if (lane == 0) sc[t] = p;
    }
    __syncthreads();

    // softmax (warp 0)
    if (wrp == 0) {
        float mx = -1e30f;
        for (int t = lane; t < cn; t += 32) mx = fmaxf(mx, sc[t]);
#pragma unroll
        for (int off = 16; off > 0; off >>= 1)
            mx = fmaxf(mx, __shfl_xor_sync(0xffffffffu, mx, off));
        float sm = 0.0f;
        for (int t = lane; t < cn; t += 32) {
            float e = __expf(sc[t] - mx);
            sc[t] = e;
            sm += e;
        }
#pragma unroll
        for (int off = 16; off > 0; off >>= 1)
            sm += __shfl_xor_sync(0xffffffffu, sm, off);
        float inv = __fdividef(1.0f, sm);
        for (int t = lane; t < cn; t += 32) sc[t] *= inv;
    }
    __syncthreads();

    // context: thread = feature u
    const int u = tid;
    float acc = 0.0f;
    const float* hgb = g_hgraph + (size_t)b * NNODES * HDIM;
    for (int t = 0; t < cn; t++)
        acc += sc[t] * __ldg(hgb + (size_t)lst[t] * HDIM + u);

    // LayerNorm
    float s1 = acc, s2 = acc * acc;
#pragma unroll
    for (int off = 16; off > 0; off >>= 1) {
        s1 += __shfl_xor_sync(0xffffffffu, s1, off);
        s2 += __shfl_xor_sync(0xffffffffu, s2, off);
    }
    if (lane == 0) { red1[wrp] = s1; red2[wrp] = s2; }
    __syncthreads();
    float tot1 = red1[0] + red1[1] + red1[2] + red1[3];
    float tot2 = red2[0] + red2[1] + red2[2] + red2[3];
    float mu = tot1 * (1.0f / HDIM);
    float var = tot2 * (1.0f / HDIM) - mu * mu;
    ha_sh[u] = __ldg(ln_g + u) * (acc - mu) * rsqrtf(var + LN_EPS) + __ldg(ln_b + u);
    __syncthreads();

    // combine (m=1): thread = output col o
    const int o = tid;
    float cacc = __ldg(comb_b + o);
#pragma unroll 8
    for (int k = 0; k < HDIM; k++)
        cacc += hl_sh[k] * g_comb_t[k * HDIM + o];
#pragma unroll 8
    for (int k = 0; k < HDIM; k++)
        cacc += ha_sh[k] * g_comb_t[(HDIM + k) * HDIM + o];
    out[row * HDIM + o] = cacc;
}

// ============================================================================
extern "C" void kernel_launch(void* const* d_in, const int* in_sizes, int n_in,
                              void* d_out, int out_size)
{
    const float* x      = (const float*)d_in[0];
    const float* adj    = (const float*)d_in[1];
    const float* h      = (const float*)d_in[2];
    const float* c      = (const float*)d_in[3];
    const float* W_ih   = (const float*)d_in[4];
    const float* W_hh   = (const float*)d_in[5];
    const float* b_ih   = (const float*)d_in[6];
    const float* b_hh   = (const float*)d_in[7];
    const float* gc_w   = (const float*)d_in[8];
    const float* gc_b   = (const float*)d_in[9];
    const float* Ws_b   = (const float*)d_in[11];
    const float* Wt_b   = (const float*)d_in[13];
    const float* v      = (const float*)d_in[14];
    const float* ln_g   = (const float*)d_in[15];
    const float* ln_b   = (const float*)d_in[16];
    const float* comb_b = (const float*)d_in[18];

    float* out = (float*)d_out;              // h_new, then c_lstm
    float* c_out = out + (size_t)BN * HDIM;

    const int scan_blocks = (BN + 7) / 8;    // 163
    prep_kernel<<<NTB + scan_blocks, 256>>>((const float*)d_in[4], (const float*)d_in[5],
                                            (const float*)d_in[10], (const float*)d_in[12],
                                            (const float*)d_in[17], adj);
    dim3 lstm_grid((BN + LNT - 1) / LNT, 4);          // 163 x 4
    lstm_gemm_kernel<<<lstm_grid, 128>>>(x, h, b_ih, b_hh);
    act_support_kernel<<<BN / 2, 128>>>(c, gc_w, c_out);          // 650
    graphconv_st_kernel<<<BN, 128>>>(gc_b, Ws_b, Wt_b);           // 1300
    attn_comb_kernel<<<BN, 128>>>(v, ln_g, ln_b, comb_b, out);    // 1300
}